// round 10
// baseline (speedup 1.0000x reference)
#include <cuda_runtime.h>
#include <cuda_bf16.h>
#include <math.h>

// ---------------------------------------------------------------------------
// PositionalEmbedding: out[n, d] = (x[n]==0 ? 0 : W[x[n], d]) + PE(n+1, d)
// N=131072, D=1024, V=50257, fp32. HBM-bound.
// R1: 194us @ 64% DRAM (MLP=1).
// R5: 158us total / 145.5us kernel @ 78.3% DRAM, 903 MB (ROWS=4 + __stcs).
// R6: ptxas rejected bare .L2::evict_last on .v4.f32 (needs .v8.b32).
// R7: same design via createpolicy + ld.global.nc.L2::cache_hint.v4.f32
//     (policy reg form is width-agnostic). ROWS=8 -> MLP_p1=8.
// ---------------------------------------------------------------------------

#define MAX_D 4096
__device__ float g_wtab[MAX_D];

// w[j] = fp32( pow( (double)fp32(1e-4), expo_j ) ) -- matches reference's
// fp32 pow bits (correctly rounded pow of the fp32-rounded base).
__global__ void build_wtab_kernel(int D) {
    int j = blockIdx.x * blockDim.x + threadIdx.x;
    if (j >= D) return;
    float jf = (float)j;
    float Df = (float)D;
    float e = (j & 1) ? (jf + 1.0f) / Df : jf / Df;   // exact (D = 2^k)
    const double B = (double)(1.0f / 10000.0f);
    g_wtab[j] = (float)pow(B, (double)e);
}

// 3-term FMA Cody-Waite reduction mod 2*pi. ang <= ~131072 -> q < 2^15;
// C1 has 8 mantissa bits so q*C1 exact; total reduction err ~5e-7 abs.
__device__ __forceinline__ float reduce_2pi(float ang) {
    const float INV2PI = 0.15915494309189535f;
    constexpr double TWO_PI = 6.28318530717958647692528676655900577;
    constexpr float C1 = 6.28125f;
    constexpr float C2 = (float)(TWO_PI - (double)C1);
    constexpr float C3 = (float)(TWO_PI - (double)C1 - (double)((float)(TWO_PI - (double)C1)));
    float q = rintf(__fmul_rn(ang, INV2PI));
    float r = __fmaf_rn(-q, C1, ang);
    r = __fmaf_rn(-q, C2, r);
    r = __fmaf_rn(-q, C3, r);
    return r;
}

__device__ __forceinline__ float pe_cos(float posf, float w) {
    return __cosf(reduce_2pi(__fmul_rn(posf, w)));    // MUFU.COS
}
__device__ __forceinline__ float pe_sin(float posf, float w) {
    return __sinf(reduce_2pi(__fmul_rn(posf, w)));    // MUFU.SIN
}

// L2 evict_last policy register (created once per thread).
__device__ __forceinline__ unsigned long long make_evict_last_policy() {
    unsigned long long pol;
    asm("createpolicy.fractional.L2::evict_last.b64 %0, 1.0;" : "=l"(pol));
    return pol;
}

// 128-bit non-coherent gather with L2 evict_last cache hint: W lines stay
// sticky in L2 while the evict-first .cs output stores pass through.
__device__ __forceinline__ float4 ldg_evict_last(const float4* p, unsigned long long pol) {
    float4 v;
    asm("ld.global.nc.L2::cache_hint.v4.f32 {%0,%1,%2,%3}, [%4], %5;"
        : "=f"(v.x), "=f"(v.y), "=f"(v.z), "=f"(v.w)
        : "l"(p), "l"(pol));
    return v;
}

#define ROWS 8

// One block handles ROWS consecutive rows; thread t owns column group t.
// All ROWS gathers issued back-to-back (unconditional) -> MLP_p1 = ROWS.
__global__ void __launch_bounds__(256) pos_emb_kernel(
    const int* __restrict__ x,
    const float* __restrict__ W,
    float* __restrict__ out,
    int D4, int N)
{
    int t = threadIdx.x;
    if (t >= D4) return;
    int row0 = blockIdx.x * ROWS;       // multiple of 8 -> 16B-aligned idx loads

    unsigned long long pol = make_evict_last_policy();

    // Block-uniform index loads (two LDG.128 for the 8 rows).
    int idx[ROWS];
    if (row0 + ROWS <= N) {
#pragma unroll
        for (int h = 0; h < ROWS / 4; h++) {
            int4 i4 = __ldg(reinterpret_cast<const int4*>(x + row0 + 4 * h));
            idx[4*h+0] = i4.x; idx[4*h+1] = i4.y; idx[4*h+2] = i4.z; idx[4*h+3] = i4.w;
        }
    } else {
#pragma unroll
        for (int r = 0; r < ROWS; r++) {
            int row = row0 + r;
            idx[r] = (row < N) ? __ldg(x + row) : 0;
        }
    }

    const float4* wt4 = reinterpret_cast<const float4*>(g_wtab);
    float4 w4 = wt4[t];                 // 4 KB table, L1-resident

    // Issue all gathers unconditionally (W[0] is valid memory; padding row
    // zero-selected afterwards). Front-batched LDG.128s -> MLP = 8.
    float4 e[ROWS];
#pragma unroll
    for (int r = 0; r < ROWS; r++) {
        const float4* wrow = reinterpret_cast<const float4*>(W) + (size_t)idx[r] * (size_t)D4;
        e[r] = ldg_evict_last(wrow + t, pol);
    }

    float4* out4 = reinterpret_cast<float4*>(out);
#pragma unroll
    for (int r = 0; r < ROWS; r++) {
        int row = row0 + r;
        if (row >= N) break;
        float posf = (float)(row + 1);
        float4 v = (idx[r] != 0) ? e[r] : make_float4(0.f, 0.f, 0.f, 0.f);
        float4 o;
        o.x = v.x + pe_cos(posf, w4.x); // j = 4t   (even -> cos)
        o.y = v.y + pe_sin(posf, w4.y); // j = 4t+1 (odd  -> sin)
        o.z = v.z + pe_cos(posf, w4.z); // j = 4t+2
        o.w = v.w + pe_sin(posf, w4.w); // j = 4t+3
        // Streaming store: output is write-once -> evict-first in L2.
        __stcs(out4 + (size_t)row * (size_t)D4 + t, o);
    }
}

extern "C" void kernel_launch(void* const* d_in, const int* in_sizes, int n_in,
                              void* d_out, int out_size) {
    int xi = 0, wi = 1;
    if (n_in >= 2 && in_sizes[0] > in_sizes[1]) { xi = 1; wi = 0; }
    const int*   x = (const int*)d_in[xi];
    const float* W = (const float*)d_in[wi];
    float* out = (float*)d_out;

    int N = in_sizes[xi];
    int D = out_size / N;               // 1024
    if (D > MAX_D) D = MAX_D;
    int D4 = D / 4;

    build_wtab_kernel<<<(D + 255) / 256, 256>>>(D);
    int nblk = (N + ROWS - 1) / ROWS;
    pos_emb_kernel<<<nblk, D4>>>(x, W, out, D4, N);
}

// round 12
// speedup vs baseline: 1.1437x; 1.1437x over previous
#include <cuda_runtime.h>
#include <cuda_bf16.h>
#include <math.h>

// ---------------------------------------------------------------------------
// PositionalEmbedding: out[n, d] = (x[n]==0 ? 0 : W[x[n], d]) + PE(n+1, d)
// N=131072, D=1024, V=50257, fp32. HBM-bound.
// R1:  194us @ 64% DRAM (MLP=1).
// R5:  158us total / 145.5us kernel @ 78.3% DRAM, 903 MB (ROWS=4 + __stcs). BEST
// R7/R10: ROWS=8 + evict_last policy REGRESSED (164us): regs 48 -> occ 55%,
//         traffic unchanged 903 MB -> evict_last neutral, dropped.
// R11: R5 structure + register-free MLP: 8 rows/block, gather rows 0-3 while
//      prefetch.global.L2 rows 4-7 (1 lane per 128B line). Front MLP=8 at
//      ROWS=4 register cost.
// ---------------------------------------------------------------------------

#define MAX_D 4096
__device__ float g_wtab[MAX_D];

// w[j] = fp32( pow( (double)fp32(1e-4), expo_j ) ) -- matches reference's
// fp32 pow bits (correctly rounded pow of the fp32-rounded base).
__global__ void build_wtab_kernel(int D) {
    int j = blockIdx.x * blockDim.x + threadIdx.x;
    if (j >= D) return;
    float jf = (float)j;
    float Df = (float)D;
    float e = (j & 1) ? (jf + 1.0f) / Df : jf / Df;   // exact (D = 2^k)
    const double B = (double)(1.0f / 10000.0f);
    g_wtab[j] = (float)pow(B, (double)e);
}

// 3-term FMA Cody-Waite reduction mod 2*pi. ang <= ~131072 -> q < 2^15;
// C1 has 8 mantissa bits so q*C1 exact; total reduction err ~5e-7 abs.
__device__ __forceinline__ float reduce_2pi(float ang) {
    const float INV2PI = 0.15915494309189535f;
    constexpr double TWO_PI = 6.28318530717958647692528676655900577;
    constexpr float C1 = 6.28125f;
    constexpr float C2 = (float)(TWO_PI - (double)C1);
    constexpr float C3 = (float)(TWO_PI - (double)C1 - (double)((float)(TWO_PI - (double)C1)));
    float q = rintf(__fmul_rn(ang, INV2PI));
    float r = __fmaf_rn(-q, C1, ang);
    r = __fmaf_rn(-q, C2, r);
    r = __fmaf_rn(-q, C3, r);
    return r;
}

__device__ __forceinline__ float pe_cos(float posf, float w) {
    return __cosf(reduce_2pi(__fmul_rn(posf, w)));    // MUFU.COS
}
__device__ __forceinline__ float pe_sin(float posf, float w) {
    return __sinf(reduce_2pi(__fmul_rn(posf, w)));    // MUFU.SIN
}

__device__ __forceinline__ void prefetch_l2(const void* p) {
    asm volatile("prefetch.global.L2 [%0];" :: "l"(p));
}

#define ROWS 8      // rows per block: 4 gathered + 4 L2-prefetched, then swap

__global__ void __launch_bounds__(256) pos_emb_kernel(
    const int* __restrict__ x,
    const float* __restrict__ W,
    float* __restrict__ out,
    int D4, int N)
{
    int t = threadIdx.x;
    if (t >= D4) return;
    int row0 = blockIdx.x * ROWS;       // multiple of 8 -> 16B-aligned idx loads

    // Block-uniform index loads (two LDG.128 for the 8 rows).
    int idx[ROWS];
    if (row0 + ROWS <= N) {
#pragma unroll
        for (int h = 0; h < ROWS / 4; h++) {
            int4 i4 = __ldg(reinterpret_cast<const int4*>(x + row0 + 4 * h));
            idx[4*h+0] = i4.x; idx[4*h+1] = i4.y; idx[4*h+2] = i4.z; idx[4*h+3] = i4.w;
        }
    } else {
#pragma unroll
        for (int r = 0; r < ROWS; r++) {
            int row = row0 + r;
            idx[r] = (row < N) ? __ldg(x + row) : 0;
        }
    }

    const float4* wt4 = reinterpret_cast<const float4*>(g_wtab);
    float4 w4 = wt4[t];                 // 4 KB table, L1-resident
    const float4* Wv = reinterpret_cast<const float4*>(W);
    float4* out4 = reinterpret_cast<float4*>(out);

    // Front-issue: 4 real gathers (rows 0-3) + 4 L2 prefetches (rows 4-7).
    // Prefetch from one lane per 128B line -> 4 line-requests per warp,
    // no destination registers. Gathers unconditional (W[0] valid; padding
    // zero-selected later) so ptxas keeps them batched.
    float4 e[4];
#pragma unroll
    for (int r = 0; r < 4; r++)
        e[r] = __ldg(Wv + (size_t)idx[r] * (size_t)D4 + t);
    if ((t & 7) == 0) {
#pragma unroll
        for (int r = 4; r < 8; r++)
            prefetch_l2(Wv + (size_t)idx[r] * (size_t)D4 + t);
    }

    // Half A: compute + streaming-store rows 0-3.
#pragma unroll
    for (int r = 0; r < 4; r++) {
        int row = row0 + r;
        if (row >= N) break;
        float posf = (float)(row + 1);
        float4 v = (idx[r] != 0) ? e[r] : make_float4(0.f, 0.f, 0.f, 0.f);
        float4 o;
        o.x = v.x + pe_cos(posf, w4.x);
        o.y = v.y + pe_sin(posf, w4.y);
        o.z = v.z + pe_cos(posf, w4.z);
        o.w = v.w + pe_sin(posf, w4.w);
        __stcs(out4 + (size_t)row * (size_t)D4 + t, o);
    }

    // Half B: gathers now L2-resident (prefetched ~a-half-tile ago).
#pragma unroll
    for (int r = 0; r < 4; r++)
        e[r] = __ldg(Wv + (size_t)idx[4 + r] * (size_t)D4 + t);

#pragma unroll
    for (int r = 0; r < 4; r++) {
        int row = row0 + 4 + r;
        if (row >= N) break;
        float posf = (float)(row + 1);
        float4 v = (idx[4 + r] != 0) ? e[r] : make_float4(0.f, 0.f, 0.f, 0.f);
        float4 o;
        o.x = v.x + pe_cos(posf, w4.x);
        o.y = v.y + pe_sin(posf, w4.y);
        o.z = v.z + pe_cos(posf, w4.z);
        o.w = v.w + pe_sin(posf, w4.w);
        __stcs(out4 + (size_t)row * (size_t)D4 + t, o);
    }
}

extern "C" void kernel_launch(void* const* d_in, const int* in_sizes, int n_in,
                              void* d_out, int out_size) {
    int xi = 0, wi = 1;
    if (n_in >= 2 && in_sizes[0] > in_sizes[1]) { xi = 1; wi = 0; }
    const int*   x = (const int*)d_in[xi];
    const float* W = (const float*)d_in[wi];
    float* out = (float*)d_out;

    int N = in_sizes[xi];
    int D = out_size / N;               // 1024
    if (D > MAX_D) D = MAX_D;
    int D4 = D / 4;

    build_wtab_kernel<<<(D + 255) / 256, 256>>>(D);
    int nblk = (N + ROWS - 1) / ROWS;
    pos_emb_kernel<<<nblk, D4>>>(x, W, out, D4, N);
}